// round 2
// baseline (speedup 1.0000x reference)
#include <cuda_runtime.h>

// FullFixedTimeCausalConstructiveAttention — B=8, L=1024, H=8, E=64, HIST=512.
// Flash-attention fp32, one thread per query row, with all QK / PV arithmetic
// done in packed fma.rn.f32x2 (2 lanes per FFMA issue slot — ptxas never emits
// this from plain C++).

#define BQ 128
#define BK 64
#define NTHREADS 128
#define B_ 8
#define L_ 1024
#define H_ 8
#define E_ 64

typedef unsigned long long ull;

__device__ __forceinline__ ull ffma2(ull a, ull b, ull c) {
    ull d;
    asm("fma.rn.f32x2 %0, %1, %2, %3;" : "=l"(d) : "l"(a), "l"(b), "l"(c));
    return d;
}
__device__ __forceinline__ ull fmul2(ull a, ull b) {
    ull d;
    asm("mul.rn.f32x2 %0, %1, %2;" : "=l"(d) : "l"(a), "l"(b));
    return d;
}
__device__ __forceinline__ ull fpack2(float lo, float hi) {
    ull d;
    asm("mov.b64 %0, {%1, %2};" : "=l"(d) : "f"(lo), "f"(hi));
    return d;
}
__device__ __forceinline__ float2 funpack2(ull a) {
    float lo, hi;
    asm("mov.b64 {%0, %1}, %2;" : "=f"(lo), "=f"(hi) : "l"(a));
    return make_float2(lo, hi);
}

__global__ __launch_bounds__(NTHREADS, 2)
void ffcca_kernel(const float* __restrict__ Q, const float* __restrict__ K,
                  const float* __restrict__ V, const float* __restrict__ Qd,
                  const float* __restrict__ Kd, const float* __restrict__ Vd,
                  const int* __restrict__ histp, float* __restrict__ Out)
{
    const int hist = *histp;                 // 512
    const int bh = blockIdx.y;
    const int b  = bh >> 3;
    const int h  = bh & 7;
    const int m0 = blockIdx.x * BQ;
    const int t  = threadIdx.x;
    const int l  = m0 + t;

    // rows of 64 floats = 16 x ulonglong2 (16B each)
    __shared__ ulonglong2 Ks[BK][16];
    __shared__ ulonglong2 Vs[BK][16];

    const size_t rowstride = (size_t)H_ * E_;               // floats per l step
    const size_t base_bh   = (size_t)b * L_ * rowstride + (size_t)h * E_;

    // ---- q_eff row into 32 packed-pair registers ----
    const float* qsrc = (l < hist) ? Q : Qd;
    const ulonglong2* qrow = (const ulonglong2*)(qsrc + base_bh + (size_t)l * rowstride);
    ull q2[32];
    #pragma unroll
    for (int i = 0; i < 16; i++) {
        ulonglong2 v = qrow[i];
        q2[2*i] = v.x; q2[2*i+1] = v.y;
    }

    // ---- diagonal replacement score (l >= hist): q_eff[l] . keys_drawn[l] ----
    float diag_s = 0.f;
    if (l >= hist) {
        const ulonglong2* kdr = (const ulonglong2*)(Kd + base_bh + (size_t)l * rowstride);
        ull d0 = 0, d1 = 0;
        #pragma unroll
        for (int i = 0; i < 16; i++) {
            ulonglong2 kk = kdr[i];
            d0 = ffma2(q2[2*i],   kk.x, d0);
            d1 = ffma2(q2[2*i+1], kk.y, d1);
        }
        float2 f0 = funpack2(d0), f1 = funpack2(d1);
        diag_s = (f0.x + f0.y) + (f1.x + f1.y);
    }

    float mrun = -1e30f, drun = 0.f;
    ull acc2[32];
    #pragma unroll
    for (int i = 0; i < 32; i++) acc2[i] = 0ull;   // (0.f, 0.f)

    const float scale = 0.125f;
    const int n_end = m0 + BQ;

    for (int n0 = 0; n0 < n_end; n0 += BK) {
        // ---- cooperative tile load ----
        const ulonglong2* kb = (const ulonglong2*)(K + base_bh + (size_t)n0 * rowstride);
        const ulonglong2* vb = (const ulonglong2*)(V + base_bh + (size_t)n0 * rowstride);
        const size_t rs16 = rowstride / 4;   // ulonglong2 per l step (=128)
        #pragma unroll
        for (int i = 0; i < 8; i++) {
            int idx = t + i * NTHREADS;
            int j = idx >> 4;
            int c = idx & 15;
            Ks[j][c] = kb[(size_t)j * rs16 + c];
            Vs[j][c] = vb[(size_t)j * rs16 + c];
        }
        __syncthreads();

        if (n0 <= l) {
            #pragma unroll 1
            for (int jc = 0; jc < BK; jc += 16) {
                if (n0 + jc > l) break;      // whole chunk masked for this row
                // ---- 16 key scores ----
                float sv[16];
                float cm = -1e30f;
                #pragma unroll
                for (int jj = 0; jj < 16; jj++) {
                    const int s = n0 + jc + jj;
                    ull d0 = 0, d1 = 0, d2 = 0, d3 = 0;
                    #pragma unroll
                    for (int i = 0; i < 16; i += 2) {
                        ulonglong2 ka = Ks[jc + jj][i];
                        ulonglong2 kbv = Ks[jc + jj][i + 1];
                        d0 = ffma2(q2[2*i],   ka.x,  d0);
                        d1 = ffma2(q2[2*i+1], ka.y,  d1);
                        d2 = ffma2(q2[2*i+2], kbv.x, d2);
                        d3 = ffma2(q2[2*i+3], kbv.y, d3);
                    }
                    float2 f0 = funpack2(d0), f1 = funpack2(d1);
                    float2 f2 = funpack2(d2), f3 = funpack2(d3);
                    float dot = ((f0.x + f0.y) + (f1.x + f1.y))
                              + ((f2.x + f2.y) + (f3.x + f3.y));
                    if (s == l && l >= hist) dot = diag_s;
                    float sc = (s <= l) ? dot * scale : -1e30f;
                    sv[jj] = sc;
                    cm = fmaxf(cm, sc);
                }
                // ---- online softmax rescale ----
                if (cm > mrun) {
                    float cf = __expf(mrun - cm);
                    mrun = cm;
                    drun *= cf;
                    ull cf2 = fpack2(cf, cf);
                    #pragma unroll
                    for (int i = 0; i < 32; i++) acc2[i] = fmul2(cf2, acc2[i]);
                }
                // ---- P.V accumulate ----
                #pragma unroll
                for (int jj = 0; jj < 16; jj++) {
                    float p = __expf(sv[jj] - mrun);
                    drun += p;
                    ull p2 = fpack2(p, p);
                    #pragma unroll
                    for (int i = 0; i < 16; i++) {
                        ulonglong2 vv = Vs[jc + jj][i];
                        acc2[2*i]   = ffma2(p2, vv.x, acc2[2*i]);
                        acc2[2*i+1] = ffma2(p2, vv.y, acc2[2*i+1]);
                    }
                }
            }
        }
        __syncthreads();
    }

    // ---- epilogue ----
    const float invd = 1.f / drun;
    float4* orow = (float4*)(Out + base_bh + (size_t)l * rowstride);
    if (l >= hist) {
        const float diagA = __expf(diag_s * scale - mrun) * invd;
        const float4* vr  = (const float4*)(V  + base_bh + (size_t)l * rowstride);
        const float4* vdr = (const float4*)(Vd + base_bh + (size_t)l * rowstride);
        #pragma unroll
        for (int i = 0; i < 16; i++) {
            float2 a0 = funpack2(acc2[2*i]);
            float2 a1 = funpack2(acc2[2*i+1]);
            float4 x = vr[i], y = vdr[i];
            float4 o;
            o.x = a0.x * invd + diagA * (y.x - x.x);
            o.y = a0.y * invd + diagA * (y.y - x.y);
            o.z = a1.x * invd + diagA * (y.z - x.z);
            o.w = a1.y * invd + diagA * (y.w - x.w);
            orow[i] = o;
        }
    } else {
        #pragma unroll
        for (int i = 0; i < 16; i++) {
            float2 a0 = funpack2(acc2[2*i]);
            float2 a1 = funpack2(acc2[2*i+1]);
            orow[i] = make_float4(a0.x * invd, a0.y * invd, a1.x * invd, a1.y * invd);
        }
    }
}

extern "C" void kernel_launch(void* const* d_in, const int* in_sizes, int n_in,
                              void* d_out, int out_size) {
    const float* Q  = (const float*)d_in[0];
    const float* K  = (const float*)d_in[1];
    const float* V  = (const float*)d_in[2];
    const float* Qd = (const float*)d_in[3];
    const float* Kd = (const float*)d_in[4];
    const float* Vd = (const float*)d_in[5];
    const int* histp = (const int*)d_in[7];
    dim3 grid(L_ / BQ, B_ * H_);
    ffcca_kernel<<<grid, NTHREADS>>>(Q, K, V, Qd, Kd, Vd, histp, (float*)d_out);
}